// round 16
// baseline (speedup 1.0000x reference)
#include <cuda_runtime.h>
#include <float.h>

#define NB     2
#define NN     8192
#define KNN    20
#define COUT   64
#define NCLASS 40
#define BN_EPS 1e-5f
#define EPT    8

// Scratch (no allocations allowed)
__device__ alignas(16) float  g_A[NB * NN];
__device__ alignas(16) float  g_B[NB * NN];
__device__ alignas(16) float4 g_pack[NB * NN];   // {x, dmin, dmax, 0}

// ---------------------------------------------------------------------------
// Compare-exchange helpers — ALL register indices compile-time constant.
// Global bitonic rule: at stage k, element i merges ascending iff (i&k)==0.
// ---------------------------------------------------------------------------
__device__ __forceinline__ void ce(float& a, float& b, bool up) {
    float mn = fminf(a, b), mx = fmaxf(a, b);
    a = up ? mn : mx;
    b = up ? mx : mn;
}

__device__ __forceinline__ void reg_merge(float v[EPT], bool d) {
    ce(v[0], v[4], d); ce(v[1], v[5], d); ce(v[2], v[6], d); ce(v[3], v[7], d);
    ce(v[0], v[2], d); ce(v[1], v[3], d); ce(v[4], v[6], d); ce(v[5], v[7], d);
    ce(v[0], v[1], d); ce(v[2], v[3], d); ce(v[4], v[5], d); ce(v[6], v[7], d);
}

__device__ __forceinline__ void sort8(float v[EPT], bool d8) {
    ce(v[0], v[1], true);  ce(v[2], v[3], false);
    ce(v[4], v[5], true);  ce(v[6], v[7], false);
    ce(v[0], v[2], true);  ce(v[1], v[3], true);
    ce(v[4], v[6], false); ce(v[5], v[7], false);
    ce(v[0], v[1], true);  ce(v[2], v[3], true);
    ce(v[4], v[5], false); ce(v[6], v[7], false);
    reg_merge(v, d8);
}

__device__ __forceinline__ void warp_merge(float v[EPT], bool d, int xm_start, int u) {
    for (int xm = xm_start; xm >= 1; xm >>= 1) {
        bool lowup = (((u & xm) == 0) == d);
        #pragma unroll
        for (int m = 0; m < EPT; m++) {
            float pv = __shfl_xor_sync(0xffffffffu, v[m], xm);
            v[m] = lowup ? fminf(v[m], pv) : fmaxf(v[m], pv);
        }
    }
    reg_merge(v, d);
}

// Subgroup-local merge over a 1024-element chunk held by 128 threads.
// __syncthreads is block-wide — all subgroups execute identical stage counts.
__device__ __forceinline__ void sub_merge(float v[EPT], float4* sA, int u,
                                          bool d, int jstart) {
    float4* sB = sA + 128;
    for (int j = jstart; j >= 256; j >>= 1) {
        sA[u] = make_float4(v[0], v[1], v[2], v[3]);
        sB[u] = make_float4(v[4], v[5], v[6], v[7]);
        __syncthreads();
        const int  pt    = u ^ (j >> 3);
        const bool lowup = (((u & (j >> 3)) == 0) == d);
        float4 pa = sA[pt], pb = sB[pt];
        v[0] = lowup ? fminf(v[0], pa.x) : fmaxf(v[0], pa.x);
        v[1] = lowup ? fminf(v[1], pa.y) : fmaxf(v[1], pa.y);
        v[2] = lowup ? fminf(v[2], pa.z) : fmaxf(v[2], pa.z);
        v[3] = lowup ? fminf(v[3], pa.w) : fmaxf(v[3], pa.w);
        v[4] = lowup ? fminf(v[4], pb.x) : fmaxf(v[4], pb.x);
        v[5] = lowup ? fminf(v[5], pb.y) : fmaxf(v[5], pb.y);
        v[6] = lowup ? fminf(v[6], pb.z) : fmaxf(v[6], pb.z);
        v[7] = lowup ? fminf(v[7], pb.w) : fmaxf(v[7], pb.w);
        __syncthreads();
    }
    warp_merge(v, d, 16, u);
}

__device__ __forceinline__ float4 f4ce(float4 a, float4 b, bool mn) {
    float4 r;
    r.x = mn ? fminf(a.x, b.x) : fmaxf(a.x, b.x);
    r.y = mn ? fminf(a.y, b.y) : fmaxf(a.y, b.y);
    r.z = mn ? fminf(a.z, b.z) : fmaxf(a.z, b.z);
    r.w = mn ? fminf(a.w, b.w) : fmaxf(a.w, b.w);
    return r;
}

// ---------------------------------------------------------------------------
// K1: fused sort (k<=1024) + k=2048 merge (validated R11/R15). grid (8,NB)x256.
// Block cx outputs post-k2048 chunk cx. Subgroup g sorts chunk cs=(cx&~1)|g;
// the k=2048 butterfly reads the partner chunk from smem; only the subgroup
// with cs==cx stores. Writes g_B. Also zeroes d_out for the atomic FC.
// ---------------------------------------------------------------------------
__global__ void __launch_bounds__(256, 1) k_sortm1(const float* __restrict__ x,
                                                   float* __restrict__ out) {
    __shared__ float4 sm[2 * 256];          // 2 chunk regions, 8KB
    const int t = threadIdx.x;
    const int cx = blockIdx.x, b = blockIdx.y;
    const int g = t >> 7, u = t & 127;
    const int cs = (cx & ~1) | g;           // chunk this subgroup processes
    if (b == 0 && cx == 0 && t < NB * NCLASS) out[t] = 0.f;

    float4* reg = sm + g * 256;

    float v[EPT];
    { const float4* src = (const float4*)(x + b * NN + cs * 1024);
      float4 a = src[u * 2], c = src[u * 2 + 1];
      v[0]=a.x; v[1]=a.y; v[2]=a.z; v[3]=a.w;
      v[4]=c.x; v[5]=c.y; v[6]=c.z; v[7]=c.w; }

    // k = 2..1024 (chunk-local, proven path)
    sort8(v, (u & 1) == 0);
    for (int k = 16; k <= 256; k <<= 1)
        warp_merge(v, (u & (k >> 3)) == 0, k >> 4, u);
    sub_merge(v, reg, u, (u & 64) == 0, 256);      // k = 512
    sub_merge(v, reg, u, (cs & 1) == 0, 512);      // k = 1024

    // k = 2048: butterfly vs partner chunk (smem), then local j<=512 merge.
    const bool asc = ((cs >> 1) & 1) == 0;         // same for both subgroups
    const bool km1 = asc == ((cs & 1) == 0);
    reg[u * 2]     = make_float4(v[0], v[1], v[2], v[3]);
    reg[u * 2 + 1] = make_float4(v[4], v[5], v[6], v[7]);
    __syncthreads();
    { const float4* pr = sm + (g ^ 1) * 256;
      float4 pa = pr[u * 2], pb = pr[u * 2 + 1];
      float4 ra = f4ce(make_float4(v[0], v[1], v[2], v[3]), pa, km1);
      float4 rb = f4ce(make_float4(v[4], v[5], v[6], v[7]), pb, km1);
      v[0]=ra.x; v[1]=ra.y; v[2]=ra.z; v[3]=ra.w;
      v[4]=rb.x; v[5]=rb.y; v[6]=rb.z; v[7]=rb.w; }
    __syncthreads();
    sub_merge(v, reg, u, asc, 512);

    if (g == (cx & 1)) {                           // this subgroup holds chunk cx
        float4* dst = (float4*)(g_B + b * NN + cx * 1024);
        dst[u * 2]     = make_float4(v[0], v[1], v[2], v[3]);
        dst[u * 2 + 1] = make_float4(v[4], v[5], v[6], v[7]);
    }
}

// ---------------------------------------------------------------------------
// Merge stage for k = 1024<<L (cross substages as load-time butterflies).
// grid (8, NB) x 128 threads. L=2: g_B->g_A (k=4096). L=3: g_A->g_B (k=8192).
// (Proven R7/R13.)
// ---------------------------------------------------------------------------
template<int L>
__global__ void __launch_bounds__(128, 1) k_merge() {
    __shared__ float4 s[256];
    const int t = threadIdx.x;
    const int b = blockIdx.y, cx = blockIdx.x;
    const float* __restrict__ srcp = (L == 2) ? g_B : g_A;
    float*       __restrict__ dstp = (L == 2) ? g_A : g_B;
    const float4* src = (const float4*)(srcp + b * NN);

    bool asc, km1, km2 = false, km3 = false;
    if (L == 2) {
        asc = ((cx >> 2) & 1) == 0;
        km1 = asc == (((cx >> 1) & 1) == 0);
        km2 = asc == ((cx & 1) == 0);
    } else {
        asc = true;
        km1 = (cx & 4) == 0;
        km2 = (cx & 2) == 0;
        km3 = (cx & 1) == 0;
    }

    float v[EPT];
    #pragma unroll
    for (int g = 0; g < 2; g++) {
        const int o = t * 2 + g;
        float4 r;
        if (L == 2) {
            float4 a0 = src[cx * 256 + o],       a1 = src[(cx ^ 1) * 256 + o];
            float4 a2 = src[(cx ^ 2) * 256 + o], a3 = src[(cx ^ 3) * 256 + o];
            r = f4ce(f4ce(a0, a2, km1), f4ce(a1, a3, km1), km2);
        } else {
            float4 a0 = src[cx * 256 + o],       a1 = src[(cx ^ 1) * 256 + o];
            float4 a2 = src[(cx ^ 2) * 256 + o], a3 = src[(cx ^ 3) * 256 + o];
            float4 a4 = src[(cx ^ 4) * 256 + o], a5 = src[(cx ^ 5) * 256 + o];
            float4 a6 = src[(cx ^ 6) * 256 + o], a7 = src[(cx ^ 7) * 256 + o];
            float4 u0 = f4ce(a0, a4, km1), u2 = f4ce(a2, a6, km1);
            float4 u1 = f4ce(a1, a5, km1), u3 = f4ce(a3, a7, km1);
            r = f4ce(f4ce(u0, u2, km2), f4ce(u1, u3, km2), km3);
        }
        v[g * 4 + 0] = r.x; v[g * 4 + 1] = r.y;
        v[g * 4 + 2] = r.z; v[g * 4 + 3] = r.w;
    }

    sub_merge(v, s, t, asc, 512);

    float4* dst = (float4*)(dstp + b * NN + cx * 1024);
    dst[t * 2]     = make_float4(v[0], v[1], v[2], v[3]);
    dst[t * 2 + 1] = make_float4(v[4], v[5], v[6], v[7]);
}

// ---------------------------------------------------------------------------
// Window v2: K-nearest window with ILP. grid (8, NB) x 256 threads.
// Block owns a 1024-chunk + ±19 halo in smem; each thread runs FOUR
// interleaved greedy chains (independent dep-chains hide LDS latency).
// Index math identical to R9 phase-E (validated). Reads g_B -> g_pack.
// ---------------------------------------------------------------------------
__global__ void __launch_bounds__(256) k_window() {
    __shared__ float sw[1024 + 2 * (KNN - 1) + 2];
    const int t = threadIdx.x;
    const int b = blockIdx.y;
    const int p0 = blockIdx.x * 1024;
    const float* __restrict__ src = g_B + b * NN;

    for (int i = t; i < 1024 + 2 * (KNN - 1); i += 256) {
        int g = p0 - (KNN - 1) + i;
        sw[i] = (g >= 0 && g < NN) ? src[g] : 0.f;   // halo garbage never read
    }
    __syncthreads();

    #define SW(l) sw[(l) + (KNN - 1)]                 // l = chunk-local index
    float xv[4], dl[4], dr[4];
    int lo[4], hi[4];
    #pragma unroll
    for (int e = 0; e < 4; e++) {
        int l = t + e * 256, p = p0 + l;
        xv[e] = SW(l);
        lo[e] = l; hi[e] = l;
        dl[e] = (p > 0)      ? (xv[e] - SW(l - 1)) : FLT_MAX;
        dr[e] = (p < NN - 1) ? (SW(l + 1) - xv[e]) : FLT_MAX;
    }
    for (int it = 1; it < KNN; it++) {
        #pragma unroll
        for (int e = 0; e < 4; e++) {
            if (dl[e] <= dr[e]) {
                lo[e]--;
                dl[e] = (p0 + lo[e] > 0) ? (xv[e] - SW(lo[e] - 1)) : FLT_MAX;
            } else {
                hi[e]++;
                dr[e] = (p0 + hi[e] < NN - 1) ? (SW(hi[e] + 1) - xv[e]) : FLT_MAX;
            }
        }
    }
    #pragma unroll
    for (int e = 0; e < 4; e++) {
        int l = t + e * 256;
        g_pack[b * NN + p0 + l] =
            make_float4(xv[e], SW(lo[e]) - xv[e], SW(hi[e]) - xv[e], 0.f);
    }
    #undef SW
}

// ---------------------------------------------------------------------------
// Reduce v2 (max & mean per (batch,channel)) + fused FC via atomicAdd.
// 512 threads, 16 points/thread fully unrolled (MLP=16). (Proven R13.)
// ---------------------------------------------------------------------------
__global__ void __launch_bounds__(512) reduce_fc(const float* __restrict__ conv_w,
                                                 const float* __restrict__ gamma,
                                                 const float* __restrict__ beta,
                                                 const float* __restrict__ mean,
                                                 const float* __restrict__ var,
                                                 const float* __restrict__ lin_w,
                                                 float* __restrict__ out) {
    __shared__ float smx[16], ssm[16], bx1, bx2;
    const int b = blockIdx.x >> 6;
    const int o = blockIdx.x & 63;
    const int t = threadIdx.x;

    const float w0 = conv_w[o * 2 + 0];
    const float w1 = conv_w[o * 2 + 1];
    const float sc = gamma[o] * rsqrtf(var[o] + BN_EPS);
    const float sh = beta[o] - mean[o] * sc;
    const bool pos = (sc >= 0.f);

    const float4* __restrict__ gp = g_pack + b * NN;
    float4 q[16];
    #pragma unroll
    for (int i = 0; i < 16; i++) q[i] = gp[t + i * 512];   // 16 loads in flight

    float mx = 0.f, sum = 0.f;
    #pragma unroll
    for (int i = 0; i < 16; i++) {
        float e = pos ? fmaxf(w0 * q[i].y, w0 * q[i].z)
                      : fminf(w0 * q[i].y, w0 * q[i].z);
        float h = fmaxf(fmaf(sc, fmaf(w1, q[i].x, e), sh), 0.f);
        mx = fmaxf(mx, h);
        sum += h;
    }
    #pragma unroll
    for (int off = 16; off > 0; off >>= 1) {
        mx  = fmaxf(mx, __shfl_xor_sync(0xffffffffu, mx, off));
        sum += __shfl_xor_sync(0xffffffffu, sum, off);
    }
    const int warp = t >> 5, lane = t & 31;
    if (lane == 0) { smx[warp] = mx; ssm[warp] = sum; }
    __syncthreads();
    if (t == 0) {
        float fmx = smx[0], fsm = ssm[0];
        #pragma unroll
        for (int w = 1; w < 16; w++) { fmx = fmaxf(fmx, smx[w]); fsm += ssm[w]; }
        bx1 = fmx;
        bx2 = fsm * (1.0f / NN);
    }
    __syncthreads();
    if (t < NCLASS) {
        const int c = t;
        float contr = lin_w[c * (2 * COUT) + o]        * bx1
                    + lin_w[c * (2 * COUT) + COUT + o] * bx2;
        atomicAdd(&out[b * NCLASS + c], contr);
    }
}

// ---------------------------------------------------------------------------
extern "C" void kernel_launch(void* const* d_in, const int* in_sizes, int n_in,
                              void* d_out, int out_size) {
    const float* x      = (const float*)d_in[0];
    const float* conv_w = (const float*)d_in[1];
    const float* gamma  = (const float*)d_in[2];
    const float* beta   = (const float*)d_in[3];
    const float* mean   = (const float*)d_in[4];
    const float* var    = (const float*)d_in[5];
    const float* lin_w  = (const float*)d_in[6];
    float* out = (float*)d_out;

    k_sortm1<<<dim3(8, NB), 256>>>(x, out);     // x   -> g_B (k <= 2048)
    k_merge<2><<<dim3(8, NB), 128>>>();         // g_B -> g_A (k = 4096)
    k_merge<3><<<dim3(8, NB), 128>>>();         // g_A -> g_B (k = 8192)
    k_window<<<dim3(8, NB), 256>>>();           // g_B -> g_pack (ILP=4)
    reduce_fc<<<NB * COUT, 512>>>(conv_w, gamma, beta, mean, var, lin_w, out);
}

// round 17
// speedup vs baseline: 1.5882x; 1.5882x over previous
#include <cuda_runtime.h>
#include <float.h>

#define NB     2
#define NN     8192
#define KNN    20
#define COUT   64
#define NCLASS 40
#define BN_EPS 1e-5f
#define EPT    8

// Scratch (no allocations allowed)
__device__ alignas(16) float  g_A[NB * NN];
__device__ alignas(16) float  g_B[NB * NN];
__device__ alignas(16) float4 g_pack[NB * NN];   // {x, dmin, dmax, 0}

// ---------------------------------------------------------------------------
// Compare-exchange helpers — ALL register indices compile-time constant.
// Global bitonic rule: at stage k, element i merges ascending iff (i&k)==0.
// ---------------------------------------------------------------------------
__device__ __forceinline__ void ce(float& a, float& b, bool up) {
    float mn = fminf(a, b), mx = fmaxf(a, b);
    a = up ? mn : mx;
    b = up ? mx : mn;
}

__device__ __forceinline__ void reg_merge(float v[EPT], bool d) {
    ce(v[0], v[4], d); ce(v[1], v[5], d); ce(v[2], v[6], d); ce(v[3], v[7], d);
    ce(v[0], v[2], d); ce(v[1], v[3], d); ce(v[4], v[6], d); ce(v[5], v[7], d);
    ce(v[0], v[1], d); ce(v[2], v[3], d); ce(v[4], v[5], d); ce(v[6], v[7], d);
}

__device__ __forceinline__ void sort8(float v[EPT], bool d8) {
    ce(v[0], v[1], true);  ce(v[2], v[3], false);
    ce(v[4], v[5], true);  ce(v[6], v[7], false);
    ce(v[0], v[2], true);  ce(v[1], v[3], true);
    ce(v[4], v[6], false); ce(v[5], v[7], false);
    ce(v[0], v[1], true);  ce(v[2], v[3], true);
    ce(v[4], v[5], false); ce(v[6], v[7], false);
    reg_merge(v, d8);
}

__device__ __forceinline__ void warp_merge(float v[EPT], bool d, int xm_start, int u) {
    for (int xm = xm_start; xm >= 1; xm >>= 1) {
        bool lowup = (((u & xm) == 0) == d);
        #pragma unroll
        for (int m = 0; m < EPT; m++) {
            float pv = __shfl_xor_sync(0xffffffffu, v[m], xm);
            v[m] = lowup ? fminf(v[m], pv) : fmaxf(v[m], pv);
        }
    }
    reg_merge(v, d);
}

// Subgroup-local merge over a 1024-element chunk held by 128 threads.
// __syncthreads is block-wide — all subgroups execute identical stage counts.
__device__ __forceinline__ void sub_merge(float v[EPT], float4* sA, int u,
                                          bool d, int jstart) {
    float4* sB = sA + 128;
    for (int j = jstart; j >= 256; j >>= 1) {
        sA[u] = make_float4(v[0], v[1], v[2], v[3]);
        sB[u] = make_float4(v[4], v[5], v[6], v[7]);
        __syncthreads();
        const int  pt    = u ^ (j >> 3);
        const bool lowup = (((u & (j >> 3)) == 0) == d);
        float4 pa = sA[pt], pb = sB[pt];
        v[0] = lowup ? fminf(v[0], pa.x) : fmaxf(v[0], pa.x);
        v[1] = lowup ? fminf(v[1], pa.y) : fmaxf(v[1], pa.y);
        v[2] = lowup ? fminf(v[2], pa.z) : fmaxf(v[2], pa.z);
        v[3] = lowup ? fminf(v[3], pa.w) : fmaxf(v[3], pa.w);
        v[4] = lowup ? fminf(v[4], pb.x) : fmaxf(v[4], pb.x);
        v[5] = lowup ? fminf(v[5], pb.y) : fmaxf(v[5], pb.y);
        v[6] = lowup ? fminf(v[6], pb.z) : fmaxf(v[6], pb.z);
        v[7] = lowup ? fminf(v[7], pb.w) : fmaxf(v[7], pb.w);
        __syncthreads();
    }
    warp_merge(v, d, 16, u);
}

__device__ __forceinline__ float4 f4ce(float4 a, float4 b, bool mn) {
    float4 r;
    r.x = mn ? fminf(a.x, b.x) : fmaxf(a.x, b.x);
    r.y = mn ? fminf(a.y, b.y) : fmaxf(a.y, b.y);
    r.z = mn ? fminf(a.z, b.z) : fmaxf(a.z, b.z);
    r.w = mn ? fminf(a.w, b.w) : fmaxf(a.w, b.w);
    return r;
}

// ---------------------------------------------------------------------------
// K1: fused sort (k<=1024) + k=2048 merge (validated R11/R15). grid (8,NB)x256.
// Block cx outputs post-k2048 chunk cx. Subgroup g sorts chunk cs=(cx&~1)|g;
// the k=2048 butterfly reads the partner chunk from smem; only the subgroup
// with cs==cx stores. Writes g_B. Also zeroes d_out for the atomic FC.
// ---------------------------------------------------------------------------
__global__ void __launch_bounds__(256, 1) k_sortm1(const float* __restrict__ x,
                                                   float* __restrict__ out) {
    __shared__ float4 sm[2 * 256];          // 2 chunk regions, 8KB
    const int t = threadIdx.x;
    const int cx = blockIdx.x, b = blockIdx.y;
    const int g = t >> 7, u = t & 127;
    const int cs = (cx & ~1) | g;           // chunk this subgroup processes
    if (b == 0 && cx == 0 && t < NB * NCLASS) out[t] = 0.f;

    float4* reg = sm + g * 256;

    float v[EPT];
    { const float4* src = (const float4*)(x + b * NN + cs * 1024);
      float4 a = src[u * 2], c = src[u * 2 + 1];
      v[0]=a.x; v[1]=a.y; v[2]=a.z; v[3]=a.w;
      v[4]=c.x; v[5]=c.y; v[6]=c.z; v[7]=c.w; }

    // k = 2..1024 (chunk-local, proven path)
    sort8(v, (u & 1) == 0);
    for (int k = 16; k <= 256; k <<= 1)
        warp_merge(v, (u & (k >> 3)) == 0, k >> 4, u);
    sub_merge(v, reg, u, (u & 64) == 0, 256);      // k = 512
    sub_merge(v, reg, u, (cs & 1) == 0, 512);      // k = 1024

    // k = 2048: butterfly vs partner chunk (smem), then local j<=512 merge.
    const bool asc = ((cs >> 1) & 1) == 0;         // same for both subgroups
    const bool km1 = asc == ((cs & 1) == 0);
    reg[u * 2]     = make_float4(v[0], v[1], v[2], v[3]);
    reg[u * 2 + 1] = make_float4(v[4], v[5], v[6], v[7]);
    __syncthreads();
    { const float4* pr = sm + (g ^ 1) * 256;
      float4 pa = pr[u * 2], pb = pr[u * 2 + 1];
      float4 ra = f4ce(make_float4(v[0], v[1], v[2], v[3]), pa, km1);
      float4 rb = f4ce(make_float4(v[4], v[5], v[6], v[7]), pb, km1);
      v[0]=ra.x; v[1]=ra.y; v[2]=ra.z; v[3]=ra.w;
      v[4]=rb.x; v[5]=rb.y; v[6]=rb.z; v[7]=rb.w; }
    __syncthreads();
    sub_merge(v, reg, u, asc, 512);

    if (g == (cx & 1)) {                           // this subgroup holds chunk cx
        float4* dst = (float4*)(g_B + b * NN + cx * 1024);
        dst[u * 2]     = make_float4(v[0], v[1], v[2], v[3]);
        dst[u * 2 + 1] = make_float4(v[4], v[5], v[6], v[7]);
    }
}

// ---------------------------------------------------------------------------
// Merge stage for k = 1024<<L (cross substages as load-time butterflies).
// grid (8, NB) x 128 threads. L=2: g_B->g_A (k=4096). L=3: g_A->g_B (k=8192).
// (Proven R7/R13.)
// ---------------------------------------------------------------------------
template<int L>
__global__ void __launch_bounds__(128, 1) k_merge() {
    __shared__ float4 s[256];
    const int t = threadIdx.x;
    const int b = blockIdx.y, cx = blockIdx.x;
    const float* __restrict__ srcp = (L == 2) ? g_B : g_A;
    float*       __restrict__ dstp = (L == 2) ? g_A : g_B;
    const float4* src = (const float4*)(srcp + b * NN);

    bool asc, km1, km2 = false, km3 = false;
    if (L == 2) {
        asc = ((cx >> 2) & 1) == 0;
        km1 = asc == (((cx >> 1) & 1) == 0);
        km2 = asc == ((cx & 1) == 0);
    } else {
        asc = true;
        km1 = (cx & 4) == 0;
        km2 = (cx & 2) == 0;
        km3 = (cx & 1) == 0;
    }

    float v[EPT];
    #pragma unroll
    for (int g = 0; g < 2; g++) {
        const int o = t * 2 + g;
        float4 r;
        if (L == 2) {
            float4 a0 = src[cx * 256 + o],       a1 = src[(cx ^ 1) * 256 + o];
            float4 a2 = src[(cx ^ 2) * 256 + o], a3 = src[(cx ^ 3) * 256 + o];
            r = f4ce(f4ce(a0, a2, km1), f4ce(a1, a3, km1), km2);
        } else {
            float4 a0 = src[cx * 256 + o],       a1 = src[(cx ^ 1) * 256 + o];
            float4 a2 = src[(cx ^ 2) * 256 + o], a3 = src[(cx ^ 3) * 256 + o];
            float4 a4 = src[(cx ^ 4) * 256 + o], a5 = src[(cx ^ 5) * 256 + o];
            float4 a6 = src[(cx ^ 6) * 256 + o], a7 = src[(cx ^ 7) * 256 + o];
            float4 u0 = f4ce(a0, a4, km1), u2 = f4ce(a2, a6, km1);
            float4 u1 = f4ce(a1, a5, km1), u3 = f4ce(a3, a7, km1);
            r = f4ce(f4ce(u0, u2, km2), f4ce(u1, u3, km2), km3);
        }
        v[g * 4 + 0] = r.x; v[g * 4 + 1] = r.y;
        v[g * 4 + 2] = r.z; v[g * 4 + 3] = r.w;
    }

    sub_merge(v, s, t, asc, 512);

    float4* dst = (float4*)(dstp + b * NN + cx * 1024);
    dst[t * 2]     = make_float4(v[0], v[1], v[2], v[3]);
    dst[t * 2 + 1] = make_float4(v[4], v[5], v[6], v[7]);
}

// ---------------------------------------------------------------------------
// Window v3 — BRANCHLESS closed form. grid (32, NB) x 256, 1 point/thread.
// For monotone dl_k = xv - x[p-k], dr_j = x[p+j] - xv, the greedy K-window's
// left-pick count is  s = sum_{k=1..19} [ dl_k <= dr_{20-k} ]  (tie rule
// dl<=dr -> left preserved by <=; OOB -> FLT_MAX). Then dmin = x[p-s]-xv,
// dmax = x[p+19-s]-xv. 38 unconditional smem loads, zero divergence.
// ---------------------------------------------------------------------------
__global__ void __launch_bounds__(256) k_window() {
    __shared__ float sw[256 + 2 * (KNN - 1) + 2];
    const int t = threadIdx.x;
    const int b = blockIdx.y;
    const int p0 = blockIdx.x * 256;
    const float* __restrict__ src = g_B + b * NN;

    for (int i = t; i < 256 + 2 * (KNN - 1); i += 256) {
        int g = p0 - (KNN - 1) + i;
        sw[i] = (g >= 0 && g < NN) ? src[g] : 0.f;   // halo garbage never read
    }
    __syncthreads();

    #define SW(l) sw[(l) + (KNN - 1)]                 // l = block-local index
    const int p  = p0 + t;                             // global position
    const float xv = SW(t);

    int s = 0;
    #pragma unroll
    for (int k = 1; k < KNN; k++) {
        // dl_k vs dr_{20-k}; OOB -> FLT_MAX (cannot both be OOB: window fits)
        float dl = (p - k >= 0)              ? (xv - SW(t - k))          : FLT_MAX;
        float dr = (p + KNN - k <= NN - 1)   ? (SW(t + KNN - k) - xv)    : FLT_MAX;
        s += (dl <= dr) ? 1 : 0;
    }

    const float dmin = SW(t - s) - xv;                 // s=0  -> 0
    const float dmax = SW(t + (KNN - 1) - s) - xv;     // s=19 -> 0
    g_pack[b * NN + p] = make_float4(xv, dmin, dmax, 0.f);
    #undef SW
}

// ---------------------------------------------------------------------------
// Reduce v2 (max & mean per (batch,channel)) + fused FC via atomicAdd.
// 512 threads, 16 points/thread fully unrolled (MLP=16). (Proven R13.)
// ---------------------------------------------------------------------------
__global__ void __launch_bounds__(512) reduce_fc(const float* __restrict__ conv_w,
                                                 const float* __restrict__ gamma,
                                                 const float* __restrict__ beta,
                                                 const float* __restrict__ mean,
                                                 const float* __restrict__ var,
                                                 const float* __restrict__ lin_w,
                                                 float* __restrict__ out) {
    __shared__ float smx[16], ssm[16], bx1, bx2;
    const int b = blockIdx.x >> 6;
    const int o = blockIdx.x & 63;
    const int t = threadIdx.x;

    const float w0 = conv_w[o * 2 + 0];
    const float w1 = conv_w[o * 2 + 1];
    const float sc = gamma[o] * rsqrtf(var[o] + BN_EPS);
    const float sh = beta[o] - mean[o] * sc;
    const bool pos = (sc >= 0.f);

    const float4* __restrict__ gp = g_pack + b * NN;
    float4 q[16];
    #pragma unroll
    for (int i = 0; i < 16; i++) q[i] = gp[t + i * 512];   // 16 loads in flight

    float mx = 0.f, sum = 0.f;
    #pragma unroll
    for (int i = 0; i < 16; i++) {
        float e = pos ? fmaxf(w0 * q[i].y, w0 * q[i].z)
                      : fminf(w0 * q[i].y, w0 * q[i].z);
        float h = fmaxf(fmaf(sc, fmaf(w1, q[i].x, e), sh), 0.f);
        mx = fmaxf(mx, h);
        sum += h;
    }
    #pragma unroll
    for (int off = 16; off > 0; off >>= 1) {
        mx  = fmaxf(mx, __shfl_xor_sync(0xffffffffu, mx, off));
        sum += __shfl_xor_sync(0xffffffffu, sum, off);
    }
    const int warp = t >> 5, lane = t & 31;
    if (lane == 0) { smx[warp] = mx; ssm[warp] = sum; }
    __syncthreads();
    if (t == 0) {
        float fmx = smx[0], fsm = ssm[0];
        #pragma unroll
        for (int w = 1; w < 16; w++) { fmx = fmaxf(fmx, smx[w]); fsm += ssm[w]; }
        bx1 = fmx;
        bx2 = fsm * (1.0f / NN);
    }
    __syncthreads();
    if (t < NCLASS) {
        const int c = t;
        float contr = lin_w[c * (2 * COUT) + o]        * bx1
                    + lin_w[c * (2 * COUT) + COUT + o] * bx2;
        atomicAdd(&out[b * NCLASS + c], contr);
    }
}

// ---------------------------------------------------------------------------
extern "C" void kernel_launch(void* const* d_in, const int* in_sizes, int n_in,
                              void* d_out, int out_size) {
    const float* x      = (const float*)d_in[0];
    const float* conv_w = (const float*)d_in[1];
    const float* gamma  = (const float*)d_in[2];
    const float* beta   = (const float*)d_in[3];
    const float* mean   = (const float*)d_in[4];
    const float* var    = (const float*)d_in[5];
    const float* lin_w  = (const float*)d_in[6];
    float* out = (float*)d_out;

    k_sortm1<<<dim3(8, NB), 256>>>(x, out);     // x   -> g_B (k <= 2048)
    k_merge<2><<<dim3(8, NB), 128>>>();         // g_B -> g_A (k = 4096)
    k_merge<3><<<dim3(8, NB), 128>>>();         // g_A -> g_B (k = 8192)
    k_window<<<dim3(32, NB), 256>>>();          // g_B -> g_pack (branchless)
    reduce_fc<<<NB * COUT, 512>>>(conv_w, gamma, beta, mean, var, lin_w, out);
}